// round 9
// baseline (speedup 1.0000x reference)
#include <cuda_runtime.h>
#include <cstdint>

#define DIMC 64
#define NPIX 512            // 9-bit single-pixel patterns
#define NBINS 4096          // 12-bit pair patterns
#define CHUNKS 12           // 32 rows per hist block
#define IMG 384
#define WORDS 12            // 384 / 32
#define BATCH 32
#define OUTW 65
#define HIST_BLOCKS (BATCH * CHUNKS)    // 384

// Static device scratch: single-pixel LUT, fully rewritten by K0 each launch.
__device__ float g_plut[NPIX * DIMC];   // 128 KB: relu(bn(conv))[pattern][ch] / (384*384)

// ---------------------------------------------------------------------------
// K0: build the 512-entry pixel LUT; zero d_out; write the marker column.
// Grid 128 x 256 = 32768 threads (one per LUT entry).
// ---------------------------------------------------------------------------
__global__ __launch_bounds__(256) void k0_kernel(
    const float* __restrict__ alpha,
    const float* __restrict__ w, const float* __restrict__ bias,
    const float* __restrict__ gamma, const float* __restrict__ beta,
    const float* __restrict__ mean, const float* __restrict__ var,
    float* __restrict__ out)
{
    int t = blockIdx.x * 256 + threadIdx.x;    // 0 .. 32767

    // output init: zeros in feature cells, marker value in column 64
    if (t < BATCH * OUTW) {
        if ((t % OUTW) == OUTW - 1) {
            uint32_t word = 0u;
#pragma unroll
            for (int j = 0; j < 32; ++j) {
                int bit = ((int)(alpha[j] * 255.0f)) & 1;
                word |= (uint32_t)bit << j;
            }
            out[t] = (__brev(word) == 0x41493234u) ? 1.0f : 0.0f;   // 'AI24'
        } else {
            out[t] = 0.0f;
        }
    }

    int c = t & (DIMC - 1);
    int p = t >> 6;                            // 9-bit pattern, bit (3*ky+kx)

    float A = gamma[c] * rsqrtf(var[c] + 1e-5f);
    float base = (bias[c] - mean[c]) * A + beta[c];

    float d = 0.f;
#pragma unroll
    for (int k = 0; k < 9; ++k)
        if ((p >> k) & 1) d += w[c * 9 + k];

    float val = fmaxf(fmaf(A, d, base), 0.f);
    g_plut[p * DIMC + c] = val * (1.0f / (384.0f * 384.0f));
}

// ---------------------------------------------------------------------------
// A: per 32-row chunk: bit-plane ballots -> 12-bit pair histogram (shared
// atomics) -> marginalize to 512 pixel bins -> contract against g_plut
// (L1-resident) -> 64 REDG float adds into d_out.
// Grid (12 chunks, 32 images) = 384 blocks x 384 threads.
// ---------------------------------------------------------------------------
__global__ __launch_bounds__(384) void hist_kernel(
    const float* __restrict__ alpha, float* __restrict__ out)
{
    __shared__ uint32_t bits[34][WORDS + 2];   // zero-padded cols, ~1.9 KB
    __shared__ int   hist[NBINS];              // 16 KB
    __shared__ int   cnt1[NPIX];               // 2 KB
    __shared__ float red[6][DIMC];             // 1.5 KB

    int tid  = threadIdx.x;
    int b    = blockIdx.y;
    int r0   = blockIdx.x * 32;
    int lane = tid & 31;
    int warp = tid >> 5;                       // 0..11 = word column

    for (int i = tid; i < NBINS; i += 384) hist[i] = 0;
    if (tid < NPIX - 384) cnt1[384 + tid] = 0;
    cnt1[tid < NPIX ? tid : 0] = 0;            // tid<384 zeroes [0,384)
    if (tid < 34) { bits[tid][0] = 0u; bits[tid][WORDS + 1] = 0u; }

    const float* img = alpha + (size_t)b * IMG * IMG;

    // batch all 34 row loads (MLP), then ballots
    float v[34];
#pragma unroll
    for (int row = 0; row < 34; ++row) {
        int g = r0 - 1 + row;
        v[row] = (g >= 0 && g < IMG) ? img[g * IMG + warp * 32 + lane] : 0.0f;
    }
#pragma unroll
    for (int row = 0; row < 34; ++row) {
        uint32_t wb = __ballot_sync(0xffffffffu, ((int)(v[row] * 255.0f)) & 1);
        if (lane == 0) bits[row][warp + 1] = wb;
    }
    __syncthreads();

    // pair-pattern shared atomics: thread = (row, word), 16 pairs each
    int r  = tid / WORDS;
    int wd = tid % WORDS;
    uint32_t p0 = bits[r][wd],     c0 = bits[r][wd + 1],     x0 = bits[r][wd + 2];
    uint32_t p1 = bits[r + 1][wd], c1 = bits[r + 1][wd + 1], x1 = bits[r + 1][wd + 2];
    uint32_t p2 = bits[r + 2][wd], c2 = bits[r + 2][wd + 1], x2 = bits[r + 2][wd + 2];

    {   // pair k=0: window straddles previous word
        uint32_t n0 = __funnelshift_r(p0, c0, 31) & 0xF;
        uint32_t n1 = __funnelshift_r(p1, c1, 31) & 0xF;
        uint32_t n2 = __funnelshift_r(p2, c2, 31) & 0xF;
        atomicAdd(&hist[n0 | (n1 << 4) | (n2 << 8)], 1);
    }
#pragma unroll
    for (int k = 1; k < 16; ++k) {
        uint32_t n0 = __funnelshift_r(c0, x0, 2 * k - 1) & 0xF;
        uint32_t n1 = __funnelshift_r(c1, x1, 2 * k - 1) & 0xF;
        uint32_t n2 = __funnelshift_r(c2, x2, 2 * k - 1) & 0xF;
        atomicAdd(&hist[n0 | (n1 << 4) | (n2 << 8)], 1);
    }
    __syncthreads();

    // marginalize 4096 pair bins -> 512 pixel bins
    // nA = cols {0,1,2} of each nibble; nB = cols {1,2,3}
    for (int p = tid; p < NBINS; p += 384) {
        int ccount = hist[p];
        if (ccount) {
            uint32_t nA = (p & 7) | ((p >> 1) & 0x38) | ((p >> 2) & 0x1C0);
            uint32_t q  = (uint32_t)p >> 1;
            uint32_t nB = (q & 7) | ((q >> 1) & 0x38) | ((q >> 2) & 0x1C0);
            atomicAdd(&cnt1[nA], ccount);
            atomicAdd(&cnt1[nB], ccount);
        }
    }
    __syncthreads();

    // contract 512 bins x 64 channels against the L1-resident pixel LUT
    int c = tid & 63;
    int g = tid >> 6;                          // 0..5
    const float* plut = g_plut + c;
    float a0 = 0.f, a1 = 0.f;
    for (int bin = g; bin < NPIX; bin += 12) {   // even split: g and g+6 chains
        a0 = fmaf((float)cnt1[bin],     plut[bin * DIMC],        a0);
        a1 = fmaf((float)cnt1[bin + 6], plut[(bin + 6) * DIMC],  a1);
    }
    red[g][c] = a0 + a1;
    __syncthreads();

    if (tid < DIMC) {
        float s = red[0][tid] + red[1][tid] + red[2][tid]
                + red[3][tid] + red[4][tid] + red[5][tid];
        atomicAdd(&out[b * OUTW + tid], s);    // REDG, no return
    }
}

// ---------------------------------------------------------------------------
extern "C" void kernel_launch(void* const* d_in, const int* in_sizes, int n_in,
                              void* d_out, int out_size)
{
    const float* alpha  = (const float*)d_in[0];
    const float* conv_w = (const float*)d_in[1];
    const float* conv_b = (const float*)d_in[2];
    const float* bn_g   = (const float*)d_in[3];
    const float* bn_b   = (const float*)d_in[4];
    const float* bn_m   = (const float*)d_in[5];
    const float* bn_v   = (const float*)d_in[6];
    float* out = (float*)d_out;

    k0_kernel<<<128, 256>>>(alpha, conv_w, conv_b, bn_g, bn_b, bn_m, bn_v, out);
    hist_kernel<<<dim3(CHUNKS, BATCH), 384>>>(alpha, out);
}